// round 16
// baseline (speedup 1.0000x reference)
#include <cuda_runtime.h>
#include <cuda_fp16.h>
#include <cstdint>

#define NODES   100000
#define HID     128
#define NCLS    32
#define INFEAT  512

// -------- scratch (static device globals; no allocation) --------
__device__ int   g_is64;
__device__ int   g_src[1600000 + 64];
__device__ int   g_dst[1600000 + 64];
__device__ int   g_csrc[1600000 + 64];
__device__ int   g_cnt[NODES];
__device__ int   g_rs[NODES + 1];
__device__ int   g_cursor[NODES];
__device__ int   g_bsum[512];
__device__ int   g_boff[512];
__device__ float g_dinv[NODES];
__device__ __align__(16) __half g_xh [(size_t)NODES * INFEAT]; // x (fp16)
__device__ __align__(16) __half g_w1h[INFEAT * HID];           // W1 (fp16)
__device__ __align__(16) __half g_hh [(size_t)NODES * HID];    // x @ W1 (fp16)
__device__ __align__(16) __half g_h1h[(size_t)NODES * HID];    // relu(agg) (fp16)
__device__ __align__(16) __half g_h2h[(size_t)NODES * NCLS];   // h1 @ W2 (fp16)

// ----------------------------------------------------------------
// setup: zero g_cnt (all blocks) + dtype detection (block 0)
// ----------------------------------------------------------------
__global__ void k_setup(const void* __restrict__ ei, int E, int n) {
    int tid = threadIdx.x;
    int i = blockIdx.x * 256 + tid;
    if (i < n) g_cnt[i] = 0;
    if (blockIdx.x == 0) {
        __shared__ int s_ok;
        if (tid == 0) s_ok = 1;
        __syncthreads();
        const long long* p = (const long long*)ei;
        int ns = E < 1024 ? E : 1024;
        int bad = 0;
        for (int q = tid; q < ns; q += 256) {
            long long v = p[q];
            if (v < 0 || v >= NODES) bad = 1;
        }
        if (bad) atomicAnd(&s_ok, 0);
        __syncthreads();
        if (tid == 0) g_is64 = s_ok;
    }
}

__global__ void k_convert(const void* __restrict__ ei, int E) {
    int i = blockIdx.x * blockDim.x + threadIdx.x;
    if (i >= E) return;
    int s, d;
    if (g_is64) {
        s = (int)((const long long*)ei)[i];
        d = (int)((const long long*)ei)[(size_t)E + i];
    } else {
        s = ((const int*)ei)[i];
        d = ((const int*)ei)[E + i];
    }
    if ((unsigned)s >= NODES) s = 0;
    if ((unsigned)d >= NODES) d = 0;
    g_src[i] = s;
    g_dst[i] = d;
    atomicAdd(&g_cnt[d], 1);
}

__global__ void k_scan_local(int n) {
    __shared__ int s[256];
    int tid = threadIdx.x;
    int i = blockIdx.x * 256 + tid;
    int v = (i < n) ? g_cnt[i] : 0;
    if (i < n) g_dinv[i] = rsqrtf((float)(v + 1));
    s[tid] = v;
    __syncthreads();
    for (int off = 1; off < 256; off <<= 1) {
        int t = (tid >= off) ? s[tid - off] : 0;
        __syncthreads();
        s[tid] += t;
        __syncthreads();
    }
    if (i < n) g_rs[i] = s[tid] - v;
    if (tid == 255) g_bsum[blockIdx.x] = s[255];
}

__global__ void k_scan_bsums(int nb) {
    __shared__ int s[512];
    int tid = threadIdx.x;
    int v = (tid < nb) ? g_bsum[tid] : 0;
    s[tid] = v;
    __syncthreads();
    for (int off = 1; off < 512; off <<= 1) {
        int t = (tid >= off) ? s[tid - off] : 0;
        __syncthreads();
        s[tid] += t;
        __syncthreads();
    }
    if (tid < nb) g_boff[tid] = s[tid] - v;
}

__global__ void k_scan_add(int n, int E) {
    int i = blockIdx.x * blockDim.x + threadIdx.x;
    if (i < n) {
        int r = g_rs[i] + g_boff[i >> 8];
        g_rs[i] = r;
        g_cursor[i] = r;
    }
    if (i == 0) g_rs[n] = E;
}

__global__ void k_scatter(int E) {
    int i = blockIdx.x * blockDim.x + threadIdx.x;
    if (i >= E) return;
    int d = g_dst[i];
    int pos = atomicAdd(&g_cursor[d], 1);
    g_csrc[pos] = g_src[i];
}

// ----------------------------------------------------------------
// helpers
// ----------------------------------------------------------------
__device__ __forceinline__ void ldsm4(uint32_t* r, uint32_t addr) {
    asm volatile("ldmatrix.sync.aligned.m8n8.x4.shared.b16 {%0,%1,%2,%3}, [%4];"
                 : "=r"(r[0]), "=r"(r[1]), "=r"(r[2]), "=r"(r[3]) : "r"(addr));
}
__device__ __forceinline__ void ldsm4t(uint32_t* r, uint32_t addr) {
    asm volatile("ldmatrix.sync.aligned.m8n8.x4.trans.shared.b16 {%0,%1,%2,%3}, [%4];"
                 : "=r"(r[0]), "=r"(r[1]), "=r"(r[2]), "=r"(r[3]) : "r"(addr));
}
__device__ __forceinline__ void mma16816(float* c, const uint32_t* a, const uint32_t* b) {
    asm volatile("mma.sync.aligned.m16n8k16.row.col.f32.f16.f16.f32 "
                 "{%0,%1,%2,%3}, {%4,%5,%6,%7}, {%8,%9}, {%0,%1,%2,%3};"
                 : "+f"(c[0]), "+f"(c[1]), "+f"(c[2]), "+f"(c[3])
                 : "r"(a[0]), "r"(a[1]), "r"(a[2]), "r"(a[3]), "r"(b[0]), "r"(b[1]));
}
__device__ __forceinline__ uint32_t packh2(float x, float y) {
    __half2 h = __floats2half2_rn(x, y);
    return *(uint32_t*)&h;
}
__device__ __forceinline__ float4 h4_to_f4(uint2 p) {
    __half2 h01 = *(__half2*)&p.x;
    __half2 h23 = *(__half2*)&p.y;
    float2 f01 = __half22float2(h01);
    float2 f23 = __half22float2(h23);
    return make_float4(f01.x, f01.y, f23.x, f23.y);
}
__device__ __forceinline__ void cp_async16(uint32_t saddr, const void* gptr, int src_bytes) {
    asm volatile("cp.async.cg.shared.global [%0], [%1], 16, %2;"
                 :: "r"(saddr), "l"(gptr), "r"(src_bytes));
}

// ----------------------------------------------------------------
// k_cvt: x (f32->f16) into g_xh, W1 (f32->f16) into g_w1h. 8 elems/thread.
// ----------------------------------------------------------------
__global__ __launch_bounds__(256) void k_cvt(const float* __restrict__ x,
                                             const float* __restrict__ W1,
                                             int nx8, int nw8) {
    int i = blockIdx.x * 256 + threadIdx.x;
    if (i < nx8) {
        float4 a = ((const float4*)x)[(size_t)i * 2];
        float4 b = ((const float4*)x)[(size_t)i * 2 + 1];
        ((uint4*)g_xh)[i] = make_uint4(packh2(a.x, a.y), packh2(a.z, a.w),
                                       packh2(b.x, b.y), packh2(b.z, b.w));
    } else if (i - nx8 < nw8) {
        int j = i - nx8;
        float4 a = ((const float4*)W1)[(size_t)j * 2];
        float4 b = ((const float4*)W1)[(size_t)j * 2 + 1];
        ((uint4*)g_w1h)[j] = make_uint4(packh2(a.x, a.y), packh2(a.z, a.w),
                                        packh2(b.x, b.y), packh2(b.z, b.w));
    }
}

// ----------------------------------------------------------------
// GEMM1 (fp16 mma, cp.async 3-stage): g_hh[M,128] = g_xh[M,512] @ g_w1h[512,128]
// BM=128, BN=64, BK=32. 256 threads = 8 warps (2 m x 4 n), warp tile 64x16.
// __launch_bounds__(256, 3): cap regs ~84 -> 3 CTAs/SM = 24 warps (R15 change).
// ----------------------------------------------------------------
#define AS_STRIDE 40    // halfs per row (32 + 8 pad); 80 B, 16B-multiple
#define BS_STRIDE 72    // halfs per row (64 + 8 pad); 144 B, 16B-multiple
#define NSTG  3
#define NTILE (INFEAT / 32)

__global__ __launch_bounds__(256, 3) void k_gemm1(int M) {
    __shared__ __align__(16) __half SA[NSTG][128 * AS_STRIDE];  // 10240 B / stage
    __shared__ __align__(16) __half SB[NSTG][32 * BS_STRIDE];   //  4608 B / stage

    const int bm   = blockIdx.y * 128;
    const int bn   = blockIdx.x * 64;
    const int tid  = threadIdx.x;
    const int wid  = tid >> 5;
    const int lane = tid & 31;
    const int warp_m = (wid >> 2) * 64;     // 0 or 64
    const int warp_n = (wid & 3) * 16;      // 0,16,32,48

    // cp.async chunk assignments (16 B = 8 halfs per chunk)
    const int a_c0   = tid * 2;
    const int b_row  = tid >> 3;
    const int b_c16  = tid & 7;

    const uint32_t sa0 = (uint32_t)__cvta_generic_to_shared(&SA[0][0]);
    const uint32_t sb0 = (uint32_t)__cvta_generic_to_shared(&SB[0][0]);

    // ldmatrix lane-derived addresses
    const int j  = lane >> 3;               // matrix id 0..3
    const int rr = lane & 7;
    const int a_lrow = warp_m + (j & 1) * 8 + rr;
    const int a_lcol = (j >> 1) * 8;
    const int b_lrow = (j & 1) * 8 + rr;
    const int b_lcol = warp_n + (j >> 1) * 8;

    float acc[4][2][4];
#pragma unroll
    for (int mi = 0; mi < 4; mi++)
#pragma unroll
        for (int ni = 0; ni < 2; ni++)
#pragma unroll
            for (int q = 0; q < 4; q++) acc[mi][ni][q] = 0.f;

    auto issue_stage = [&](int t) {
        const int s  = t % NSTG;
        const int k0 = t * 32;
        const uint32_t sa = sa0 + s * (128 * AS_STRIDE * 2);
        const uint32_t sb = sb0 + s * (32 * BS_STRIDE * 2);
#pragma unroll
        for (int q = 0; q < 2; q++) {
            int c   = a_c0 + q;
            int row = c >> 2;
            int c16 = c & 3;
            int m   = bm + row;
            int ok  = (m < M) ? 16 : 0;
            int mc  = (m < M) ? m : (M - 1);
            cp_async16(sa + row * (AS_STRIDE * 2) + c16 * 16,
                       g_xh + (size_t)mc * INFEAT + k0 + c16 * 8, ok);
        }
        cp_async16(sb + b_row * (BS_STRIDE * 2) + b_c16 * 16,
                   g_w1h + (size_t)(k0 + b_row) * HID + bn + b_c16 * 8, 16);
        asm volatile("cp.async.commit_group;");
    };

    issue_stage(0);
    issue_stage(1);

    for (int t = 0; t < NTILE; t++) {
        // tail: at t = NTILE-1 only ONE group (stage t itself) is pending,
        // so wait_group 1 would NOT wait for it -> race. Drain fully instead.
        if (t + 1 < NTILE)
            asm volatile("cp.async.wait_group 1;");
        else
            asm volatile("cp.async.wait_group 0;");
        __syncthreads();                       // stage t visible to all warps

        if (t + 2 < NTILE) issue_stage(t + 2); // overwrites slot (t-1)%3: safe past barrier

        const int s = t % NSTG;
        const uint32_t sa = sa0 + s * (128 * AS_STRIDE * 2);
        const uint32_t sb = sb0 + s * (32 * BS_STRIDE * 2);
#pragma unroll
        for (int kk = 0; kk < 2; kk++) {
            uint32_t af[4][4];
#pragma unroll
            for (int mi = 0; mi < 4; mi++)
                ldsm4(af[mi], sa +
                      (uint32_t)(((a_lrow + mi * 16) * AS_STRIDE + kk * 16 + a_lcol) * 2));
            uint32_t tB[4];
            ldsm4t(tB, sb +
                   (uint32_t)(((kk * 16 + b_lrow) * BS_STRIDE + b_lcol) * 2));
            uint32_t bf[2][2] = {{tB[0], tB[1]}, {tB[2], tB[3]}};
#pragma unroll
            for (int mi = 0; mi < 4; mi++)
#pragma unroll
                for (int ni = 0; ni < 2; ni++)
                    mma16816(acc[mi][ni], af[mi], bf[ni]);
        }
        __syncthreads();                       // all reads of stage t done before reuse
    }

    const int g = lane >> 2;
    const int c = lane & 3;
#pragma unroll
    for (int mi = 0; mi < 4; mi++) {
#pragma unroll
        for (int ni = 0; ni < 2; ni++) {
            int row0 = bm + warp_m + mi * 16 + g;
            int col  = bn + warp_n + ni * 8 + c * 2;
            if (row0 < M)
                *(__half2*)&g_hh[(size_t)row0 * HID + col] =
                    __floats2half2_rn(acc[mi][ni][0], acc[mi][ni][1]);
            int row1 = row0 + 8;
            if (row1 < M)
                *(__half2*)&g_hh[(size_t)row1 * HID + col] =
                    __floats2half2_rn(acc[mi][ni][2], acc[mi][ni][3]);
        }
    }
}

// ----------------------------------------------------------------
// agg1: one warp per dst node; each lane covers 4 feats (8B loads).
// h1[d] = relu(dinv[d] * sum_s dinv[s]*h[s] + dinv[d]^2 * h[d] + b1)  -> fp16
// ----------------------------------------------------------------
__global__ __launch_bounds__(256) void k_agg1(const float* __restrict__ b1, int n) {
    int gtid = blockIdx.x * blockDim.x + threadIdx.x;
    int d    = gtid >> 5;
    int lane = gtid & 31;
    if (d >= n) return;

    int rs = g_rs[d], re = g_rs[d + 1];
    float4 acc = make_float4(0.f, 0.f, 0.f, 0.f);
    int e = rs;
    for (; e + 1 < re; e += 2) {
        int s0 = g_csrc[e];
        int s1 = g_csrc[e + 1];
        float w0 = g_dinv[s0];
        float w1 = g_dinv[s1];
        float4 v0 = h4_to_f4(*(const uint2*)&g_hh[(size_t)s0 * HID + lane * 4]);
        float4 v1 = h4_to_f4(*(const uint2*)&g_hh[(size_t)s1 * HID + lane * 4]);
        acc.x = fmaf(w0, v0.x, acc.x); acc.y = fmaf(w0, v0.y, acc.y);
        acc.z = fmaf(w0, v0.z, acc.z); acc.w = fmaf(w0, v0.w, acc.w);
        acc.x = fmaf(w1, v1.x, acc.x); acc.y = fmaf(w1, v1.y, acc.y);
        acc.z = fmaf(w1, v1.z, acc.z); acc.w = fmaf(w1, v1.w, acc.w);
    }
    if (e < re) {
        int s0 = g_csrc[e];
        float w0 = g_dinv[s0];
        float4 v0 = h4_to_f4(*(const uint2*)&g_hh[(size_t)s0 * HID + lane * 4]);
        acc.x = fmaf(w0, v0.x, acc.x); acc.y = fmaf(w0, v0.y, acc.y);
        acc.z = fmaf(w0, v0.z, acc.z); acc.w = fmaf(w0, v0.w, acc.w);
    }

    float di = g_dinv[d];
    float sl = di * di;
    float4 hv = h4_to_f4(*(const uint2*)&g_hh[(size_t)d * HID + lane * 4]);
    float4 bb = *(const float4*)&b1[lane * 4];
    float rx = fmaxf(fmaf(di, acc.x, fmaf(sl, hv.x, bb.x)), 0.f);
    float ry = fmaxf(fmaf(di, acc.y, fmaf(sl, hv.y, bb.y)), 0.f);
    float rz = fmaxf(fmaf(di, acc.z, fmaf(sl, hv.z, bb.z)), 0.f);
    float rw = fmaxf(fmaf(di, acc.w, fmaf(sl, hv.w, bb.w)), 0.f);
    uint2 o;
    o.x = packh2(rx, ry);
    o.y = packh2(rz, rw);
    *(uint2*)&g_h1h[(size_t)d * HID + lane * 4] = o;
}

// ----------------------------------------------------------------
// GEMM2: g_h2h[M,32] = g_h1h[M,128] @ W2[128,32]  (fp32 math, fp16 I/O)
// ----------------------------------------------------------------
__global__ __launch_bounds__(256) void k_gemm2(const float* __restrict__ W, int M) {
    __shared__ float Ws[HID * NCLS];
    __shared__ float As[64 * HID];

    const int bm  = blockIdx.x * 64;
    const int tid = threadIdx.x;

    for (int i = tid; i < HID * NCLS / 4; i += 256)
        ((float4*)Ws)[i] = ((const float4*)W)[i];
    for (int i = tid; i < 64 * HID / 4; i += 256) {
        int r = i >> 5;
        int m = bm + r;
        float4 v = make_float4(0.f, 0.f, 0.f, 0.f);
        if (m < M) v = h4_to_f4(((const uint2*)g_h1h)[(size_t)m * 32 + (i & 31)]);
        ((float4*)As)[i] = v;
    }
    __syncthreads();

    const int col = tid & 31;
    const int r0  = (tid >> 5) * 8;
    float acc[8];
#pragma unroll
    for (int r = 0; r < 8; r++) acc[r] = 0.f;

    for (int k = 0; k < HID; k++) {
        float w = Ws[k * NCLS + col];
#pragma unroll
        for (int r = 0; r < 8; r++)
            acc[r] = fmaf(As[(r0 + r) * HID + k], w, acc[r]);
    }
#pragma unroll
    for (int r = 0; r < 8; r++) {
        int m = bm + r0 + r;
        if (m < M) g_h2h[(size_t)m * NCLS + col] = __float2half_rn(acc[r]);
    }
}

// ----------------------------------------------------------------
// agg2: one warp per dst node (32 feats), write final fp32 out
// ----------------------------------------------------------------
__global__ __launch_bounds__(256) void k_agg2(const float* __restrict__ b2,
                                              float* __restrict__ out, int n) {
    int gtid = blockIdx.x * blockDim.x + threadIdx.x;
    int d    = gtid >> 5;
    int lane = gtid & 31;
    if (d >= n) return;

    int rs = g_rs[d], re = g_rs[d + 1];
    float acc = 0.f;
    int e = rs;
    for (; e + 1 < re; e += 2) {
        int s0 = g_csrc[e];
        int s1 = g_csrc[e + 1];
        float w0 = g_dinv[s0];
        float w1 = g_dinv[s1];
        float v0 = __half2float(g_h2h[(size_t)s0 * NCLS + lane]);
        float v1 = __half2float(g_h2h[(size_t)s1 * NCLS + lane]);
        acc = fmaf(w0, v0, acc);
        acc = fmaf(w1, v1, acc);
    }
    if (e < re) {
        int s0 = g_csrc[e];
        acc = fmaf(g_dinv[s0], __half2float(g_h2h[(size_t)s0 * NCLS + lane]), acc);
    }

    float di = g_dinv[d];
    float hv = __half2float(g_h2h[(size_t)d * NCLS + lane]);
    out[(size_t)d * NCLS + lane] = fmaf(di, acc, fmaf(di * di, hv, b2[lane]));
}

// ----------------------------------------------------------------
// launch: side stream = cvt -> gemm1; main stream = CSR build
// ----------------------------------------------------------------
extern "C" void kernel_launch(void* const* d_in, const int* in_sizes, int n_in,
                              void* d_out, int out_size) {
    const float* x  = (const float*)d_in[0];
    const void*  ei = d_in[1];
    const float* W1 = (const float*)d_in[2];
    const float* b1 = (const float*)d_in[3];
    const float* W2 = (const float*)d_in[4];
    const float* b2 = (const float*)d_in[5];
    float* out = (float*)d_out;

    const int M = in_sizes[0] / INFEAT;     // 100000
    const int E = in_sizes[1] / 2;          // 1600000

    const int T  = 256;
    const int nb = (M + 255) / 256;

    static cudaStream_t s_side = nullptr;
    static cudaEvent_t  ev_fork = nullptr, ev_join = nullptr;
    if (!s_side) {
        cudaStreamCreateWithFlags(&s_side, cudaStreamNonBlocking);
        cudaEventCreateWithFlags(&ev_fork, cudaEventDisableTiming);
        cudaEventCreateWithFlags(&ev_join, cudaEventDisableTiming);
    }

    // fork: convert + GEMM1 (depend only on x, W1) on side stream
    cudaEventRecord(ev_fork, 0);
    cudaStreamWaitEvent(s_side, ev_fork, 0);
    {
        int nx8 = M * INFEAT / 8;
        int nw8 = INFEAT * HID / 8;
        int gc  = (nx8 + nw8 + T - 1) / T;
        k_cvt<<<gc, T, 0, s_side>>>(x, W1, nx8, nw8);
        dim3 grid(2, (M + 127) / 128);
        k_gemm1<<<grid, T, 0, s_side>>>(M);
    }
    cudaEventRecord(ev_join, s_side);

    // main stream: edge parse + CSR build (+dinv)
    k_setup<<<nb, 256>>>(ei, E, M);
    k_convert<<<(E + T - 1) / T, T>>>(ei, E);
    k_scan_local<<<nb, 256>>>(M);
    k_scan_bsums<<<1, 512>>>(nb);
    k_scan_add<<<(M + T - 1) / T, T>>>(M, E);
    k_scatter<<<(E + T - 1) / T, T>>>(E);

    // join: aggregation needs both GEMM1 and CSR
    cudaStreamWaitEvent(0, ev_join, 0);

    k_agg1<<<((long long)M * 32 + T - 1) / T, T>>>(b1, M);
    k_gemm2<<<(M + 63) / 64, T>>>(W2, M);
    k_agg2<<<((long long)M * 32 + T - 1) / T, T>>>(b2, out, M);
}

// round 17
// speedup vs baseline: 1.0152x; 1.0152x over previous
#include <cuda_runtime.h>
#include <cuda_fp16.h>
#include <cstdint>

#define NODES   100000
#define HID     128
#define NCLS    32
#define INFEAT  512

// -------- scratch (static device globals; no allocation) --------
__device__ int   g_is64;
__device__ int   g_src[1600000 + 64];
__device__ int   g_dst[1600000 + 64];
__device__ int   g_csrc[1600000 + 64];
__device__ int   g_cnt[NODES];
__device__ int   g_rs[NODES + 1];
__device__ int   g_cursor[NODES];
__device__ int   g_bsum[512];
__device__ int   g_boff[512];
__device__ float g_dinv[NODES];
__device__ __align__(16) __half g_xh [(size_t)NODES * INFEAT]; // x (fp16)
__device__ __align__(16) __half g_w1h[INFEAT * HID];           // W1 (fp16)
__device__ __align__(16) __half g_hh [(size_t)NODES * HID];    // x @ W1 (fp16)
__device__ __align__(16) __half g_h1h[(size_t)NODES * HID];    // relu(agg) (fp16)
__device__ __align__(16) __half g_h2h[(size_t)NODES * NCLS];   // h1 @ W2 (fp16)

// ----------------------------------------------------------------
// setup: zero g_cnt (all blocks) + dtype detection (block 0)
// ----------------------------------------------------------------
__global__ void k_setup(const void* __restrict__ ei, int E, int n) {
    int tid = threadIdx.x;
    int i = blockIdx.x * 256 + tid;
    if (i < n) g_cnt[i] = 0;
    if (blockIdx.x == 0) {
        __shared__ int s_ok;
        if (tid == 0) s_ok = 1;
        __syncthreads();
        const long long* p = (const long long*)ei;
        int ns = E < 1024 ? E : 1024;
        int bad = 0;
        for (int q = tid; q < ns; q += 256) {
            long long v = p[q];
            if (v < 0 || v >= NODES) bad = 1;
        }
        if (bad) atomicAnd(&s_ok, 0);
        __syncthreads();
        if (tid == 0) g_is64 = s_ok;
    }
}

__global__ void k_convert(const void* __restrict__ ei, int E) {
    int i = blockIdx.x * blockDim.x + threadIdx.x;
    if (i >= E) return;
    int s, d;
    if (g_is64) {
        s = (int)((const long long*)ei)[i];
        d = (int)((const long long*)ei)[(size_t)E + i];
    } else {
        s = ((const int*)ei)[i];
        d = ((const int*)ei)[E + i];
    }
    if ((unsigned)s >= NODES) s = 0;
    if ((unsigned)d >= NODES) d = 0;
    g_src[i] = s;
    g_dst[i] = d;
    atomicAdd(&g_cnt[d], 1);
}

__global__ void k_scan_local(int n) {
    __shared__ int s[256];
    int tid = threadIdx.x;
    int i = blockIdx.x * 256 + tid;
    int v = (i < n) ? g_cnt[i] : 0;
    if (i < n) g_dinv[i] = rsqrtf((float)(v + 1));
    s[tid] = v;
    __syncthreads();
    for (int off = 1; off < 256; off <<= 1) {
        int t = (tid >= off) ? s[tid - off] : 0;
        __syncthreads();
        s[tid] += t;
        __syncthreads();
    }
    if (i < n) g_rs[i] = s[tid] - v;
    if (tid == 255) g_bsum[blockIdx.x] = s[255];
}

__global__ void k_scan_bsums(int nb) {
    __shared__ int s[512];
    int tid = threadIdx.x;
    int v = (tid < nb) ? g_bsum[tid] : 0;
    s[tid] = v;
    __syncthreads();
    for (int off = 1; off < 512; off <<= 1) {
        int t = (tid >= off) ? s[tid - off] : 0;
        __syncthreads();
        s[tid] += t;
        __syncthreads();
    }
    if (tid < nb) g_boff[tid] = s[tid] - v;
}

__global__ void k_scan_add(int n, int E) {
    int i = blockIdx.x * blockDim.x + threadIdx.x;
    if (i < n) {
        int r = g_rs[i] + g_boff[i >> 8];
        g_rs[i] = r;
        g_cursor[i] = r;
    }
    if (i == 0) g_rs[n] = E;
}

__global__ void k_scatter(int E) {
    int i = blockIdx.x * blockDim.x + threadIdx.x;
    if (i >= E) return;
    int d = g_dst[i];
    int pos = atomicAdd(&g_cursor[d], 1);
    g_csrc[pos] = g_src[i];
}

// ----------------------------------------------------------------
// helpers
// ----------------------------------------------------------------
__device__ __forceinline__ void ldsm4(uint32_t* r, uint32_t addr) {
    asm volatile("ldmatrix.sync.aligned.m8n8.x4.shared.b16 {%0,%1,%2,%3}, [%4];"
                 : "=r"(r[0]), "=r"(r[1]), "=r"(r[2]), "=r"(r[3]) : "r"(addr));
}
__device__ __forceinline__ void ldsm4t(uint32_t* r, uint32_t addr) {
    asm volatile("ldmatrix.sync.aligned.m8n8.x4.trans.shared.b16 {%0,%1,%2,%3}, [%4];"
                 : "=r"(r[0]), "=r"(r[1]), "=r"(r[2]), "=r"(r[3]) : "r"(addr));
}
__device__ __forceinline__ void mma16816(float* c, const uint32_t* a, const uint32_t* b) {
    asm volatile("mma.sync.aligned.m16n8k16.row.col.f32.f16.f16.f32 "
                 "{%0,%1,%2,%3}, {%4,%5,%6,%7}, {%8,%9}, {%0,%1,%2,%3};"
                 : "+f"(c[0]), "+f"(c[1]), "+f"(c[2]), "+f"(c[3])
                 : "r"(a[0]), "r"(a[1]), "r"(a[2]), "r"(a[3]), "r"(b[0]), "r"(b[1]));
}
__device__ __forceinline__ uint32_t packh2(float x, float y) {
    __half2 h = __floats2half2_rn(x, y);
    return *(uint32_t*)&h;
}
__device__ __forceinline__ float4 h4_to_f4(uint2 p) {
    __half2 h01 = *(__half2*)&p.x;
    __half2 h23 = *(__half2*)&p.y;
    float2 f01 = __half22float2(h01);
    float2 f23 = __half22float2(h23);
    return make_float4(f01.x, f01.y, f23.x, f23.y);
}
__device__ __forceinline__ void cp_async16(uint32_t saddr, const void* gptr, int src_bytes) {
    asm volatile("cp.async.cg.shared.global [%0], [%1], 16, %2;"
                 :: "r"(saddr), "l"(gptr), "r"(src_bytes));
}

// ----------------------------------------------------------------
// k_cvt: x (f32->f16) into g_xh, W1 (f32->f16) into g_w1h. 8 elems/thread.
// ----------------------------------------------------------------
__global__ __launch_bounds__(256) void k_cvt(const float* __restrict__ x,
                                             const float* __restrict__ W1,
                                             int nx8, int nw8) {
    int i = blockIdx.x * 256 + threadIdx.x;
    if (i < nx8) {
        float4 a = ((const float4*)x)[(size_t)i * 2];
        float4 b = ((const float4*)x)[(size_t)i * 2 + 1];
        ((uint4*)g_xh)[i] = make_uint4(packh2(a.x, a.y), packh2(a.z, a.w),
                                       packh2(b.x, b.y), packh2(b.z, b.w));
    } else if (i - nx8 < nw8) {
        int j = i - nx8;
        float4 a = ((const float4*)W1)[(size_t)j * 2];
        float4 b = ((const float4*)W1)[(size_t)j * 2 + 1];
        ((uint4*)g_w1h)[j] = make_uint4(packh2(a.x, a.y), packh2(a.z, a.w),
                                        packh2(b.x, b.y), packh2(b.z, b.w));
    }
}

// ----------------------------------------------------------------
// GEMM1 (fp16 mma, cp.async 3-stage): g_hh[M,128] = g_xh[M,512] @ g_w1h[512,128]
// BM=128, BN=64, BK=32. 256 threads = 8 warps (2 m x 4 n), warp tile 64x16.
// ----------------------------------------------------------------
#define AS_STRIDE 40    // halfs per row (32 + 8 pad); 80 B, 16B-multiple
#define BS_STRIDE 72    // halfs per row (64 + 8 pad); 144 B, 16B-multiple
#define NSTG  3
#define NTILE (INFEAT / 32)

__global__ __launch_bounds__(256) void k_gemm1(int M) {
    __shared__ __align__(16) __half SA[NSTG][128 * AS_STRIDE];  // 10240 B / stage
    __shared__ __align__(16) __half SB[NSTG][32 * BS_STRIDE];   //  4608 B / stage

    const int bm   = blockIdx.y * 128;
    const int bn   = blockIdx.x * 64;
    const int tid  = threadIdx.x;
    const int wid  = tid >> 5;
    const int lane = tid & 31;
    const int warp_m = (wid >> 2) * 64;     // 0 or 64
    const int warp_n = (wid & 3) * 16;      // 0,16,32,48

    // cp.async chunk assignments (16 B = 8 halfs per chunk)
    const int a_c0   = tid * 2;
    const int b_row  = tid >> 3;
    const int b_c16  = tid & 7;

    const uint32_t sa0 = (uint32_t)__cvta_generic_to_shared(&SA[0][0]);
    const uint32_t sb0 = (uint32_t)__cvta_generic_to_shared(&SB[0][0]);

    // ldmatrix lane-derived addresses
    const int j  = lane >> 3;               // matrix id 0..3
    const int rr = lane & 7;
    const int a_lrow = warp_m + (j & 1) * 8 + rr;
    const int a_lcol = (j >> 1) * 8;
    const int b_lrow = (j & 1) * 8 + rr;
    const int b_lcol = warp_n + (j >> 1) * 8;

    float acc[4][2][4];
#pragma unroll
    for (int mi = 0; mi < 4; mi++)
#pragma unroll
        for (int ni = 0; ni < 2; ni++)
#pragma unroll
            for (int q = 0; q < 4; q++) acc[mi][ni][q] = 0.f;

    auto issue_stage = [&](int t) {
        const int s  = t % NSTG;
        const int k0 = t * 32;
        const uint32_t sa = sa0 + s * (128 * AS_STRIDE * 2);
        const uint32_t sb = sb0 + s * (32 * BS_STRIDE * 2);
#pragma unroll
        for (int q = 0; q < 2; q++) {
            int c   = a_c0 + q;
            int row = c >> 2;
            int c16 = c & 3;
            int m   = bm + row;
            int ok  = (m < M) ? 16 : 0;
            int mc  = (m < M) ? m : (M - 1);
            cp_async16(sa + row * (AS_STRIDE * 2) + c16 * 16,
                       g_xh + (size_t)mc * INFEAT + k0 + c16 * 8, ok);
        }
        cp_async16(sb + b_row * (BS_STRIDE * 2) + b_c16 * 16,
                   g_w1h + (size_t)(k0 + b_row) * HID + bn + b_c16 * 8, 16);
        asm volatile("cp.async.commit_group;");
    };

    issue_stage(0);
    issue_stage(1);

    for (int t = 0; t < NTILE; t++) {
        // tail: at t = NTILE-1 only ONE group (stage t itself) is pending,
        // so wait_group 1 would NOT wait for it -> race. Drain fully instead.
        if (t + 1 < NTILE)
            asm volatile("cp.async.wait_group 1;");
        else
            asm volatile("cp.async.wait_group 0;");
        __syncthreads();                       // stage t visible to all warps

        if (t + 2 < NTILE) issue_stage(t + 2); // overwrites slot (t-1)%3: safe past barrier

        const int s = t % NSTG;
        const uint32_t sa = sa0 + s * (128 * AS_STRIDE * 2);
        const uint32_t sb = sb0 + s * (32 * BS_STRIDE * 2);
#pragma unroll
        for (int kk = 0; kk < 2; kk++) {
            uint32_t af[4][4];
#pragma unroll
            for (int mi = 0; mi < 4; mi++)
                ldsm4(af[mi], sa +
                      (uint32_t)(((a_lrow + mi * 16) * AS_STRIDE + kk * 16 + a_lcol) * 2));
            uint32_t tB[4];
            ldsm4t(tB, sb +
                   (uint32_t)(((kk * 16 + b_lrow) * BS_STRIDE + b_lcol) * 2));
            uint32_t bf[2][2] = {{tB[0], tB[1]}, {tB[2], tB[3]}};
#pragma unroll
            for (int mi = 0; mi < 4; mi++)
#pragma unroll
                for (int ni = 0; ni < 2; ni++)
                    mma16816(acc[mi][ni], af[mi], bf[ni]);
        }
        __syncthreads();                       // all reads of stage t done before reuse
    }

    const int g = lane >> 2;
    const int c = lane & 3;
#pragma unroll
    for (int mi = 0; mi < 4; mi++) {
#pragma unroll
        for (int ni = 0; ni < 2; ni++) {
            int row0 = bm + warp_m + mi * 16 + g;
            int col  = bn + warp_n + ni * 8 + c * 2;
            if (row0 < M)
                *(__half2*)&g_hh[(size_t)row0 * HID + col] =
                    __floats2half2_rn(acc[mi][ni][0], acc[mi][ni][1]);
            int row1 = row0 + 8;
            if (row1 < M)
                *(__half2*)&g_hh[(size_t)row1 * HID + col] =
                    __floats2half2_rn(acc[mi][ni][2], acc[mi][ni][3]);
        }
    }
}

// ----------------------------------------------------------------
// agg1: one warp per dst node; each lane covers 4 feats (8B loads).
// h1[d] = relu(dinv[d] * sum_s dinv[s]*h[s] + dinv[d]^2 * h[d] + b1)  -> fp16
// ----------------------------------------------------------------
__global__ __launch_bounds__(256) void k_agg1(const float* __restrict__ b1, int n) {
    int gtid = blockIdx.x * blockDim.x + threadIdx.x;
    int d    = gtid >> 5;
    int lane = gtid & 31;
    if (d >= n) return;

    int rs = g_rs[d], re = g_rs[d + 1];
    float4 acc = make_float4(0.f, 0.f, 0.f, 0.f);
    int e = rs;
    for (; e + 1 < re; e += 2) {
        int s0 = g_csrc[e];
        int s1 = g_csrc[e + 1];
        float w0 = g_dinv[s0];
        float w1 = g_dinv[s1];
        float4 v0 = h4_to_f4(*(const uint2*)&g_hh[(size_t)s0 * HID + lane * 4]);
        float4 v1 = h4_to_f4(*(const uint2*)&g_hh[(size_t)s1 * HID + lane * 4]);
        acc.x = fmaf(w0, v0.x, acc.x); acc.y = fmaf(w0, v0.y, acc.y);
        acc.z = fmaf(w0, v0.z, acc.z); acc.w = fmaf(w0, v0.w, acc.w);
        acc.x = fmaf(w1, v1.x, acc.x); acc.y = fmaf(w1, v1.y, acc.y);
        acc.z = fmaf(w1, v1.z, acc.z); acc.w = fmaf(w1, v1.w, acc.w);
    }
    if (e < re) {
        int s0 = g_csrc[e];
        float w0 = g_dinv[s0];
        float4 v0 = h4_to_f4(*(const uint2*)&g_hh[(size_t)s0 * HID + lane * 4]);
        acc.x = fmaf(w0, v0.x, acc.x); acc.y = fmaf(w0, v0.y, acc.y);
        acc.z = fmaf(w0, v0.z, acc.z); acc.w = fmaf(w0, v0.w, acc.w);
    }

    float di = g_dinv[d];
    float sl = di * di;
    float4 hv = h4_to_f4(*(const uint2*)&g_hh[(size_t)d * HID + lane * 4]);
    float4 bb = *(const float4*)&b1[lane * 4];
    float rx = fmaxf(fmaf(di, acc.x, fmaf(sl, hv.x, bb.x)), 0.f);
    float ry = fmaxf(fmaf(di, acc.y, fmaf(sl, hv.y, bb.y)), 0.f);
    float rz = fmaxf(fmaf(di, acc.z, fmaf(sl, hv.z, bb.z)), 0.f);
    float rw = fmaxf(fmaf(di, acc.w, fmaf(sl, hv.w, bb.w)), 0.f);
    uint2 o;
    o.x = packh2(rx, ry);
    o.y = packh2(rz, rw);
    *(uint2*)&g_h1h[(size_t)d * HID + lane * 4] = o;
}

// ----------------------------------------------------------------
// GEMM2: g_h2h[M,32] = g_h1h[M,128] @ W2[128,32]  (fp32 math, fp16 I/O)
// ----------------------------------------------------------------
__global__ __launch_bounds__(256) void k_gemm2(const float* __restrict__ W, int M) {
    __shared__ float Ws[HID * NCLS];
    __shared__ float As[64 * HID];

    const int bm  = blockIdx.x * 64;
    const int tid = threadIdx.x;

    for (int i = tid; i < HID * NCLS / 4; i += 256)
        ((float4*)Ws)[i] = ((const float4*)W)[i];
    for (int i = tid; i < 64 * HID / 4; i += 256) {
        int r = i >> 5;
        int m = bm + r;
        float4 v = make_float4(0.f, 0.f, 0.f, 0.f);
        if (m < M) v = h4_to_f4(((const uint2*)g_h1h)[(size_t)m * 32 + (i & 31)]);
        ((float4*)As)[i] = v;
    }
    __syncthreads();

    const int col = tid & 31;
    const int r0  = (tid >> 5) * 8;
    float acc[8];
#pragma unroll
    for (int r = 0; r < 8; r++) acc[r] = 0.f;

    for (int k = 0; k < HID; k++) {
        float w = Ws[k * NCLS + col];
#pragma unroll
        for (int r = 0; r < 8; r++)
            acc[r] = fmaf(As[(r0 + r) * HID + k], w, acc[r]);
    }
#pragma unroll
    for (int r = 0; r < 8; r++) {
        int m = bm + r0 + r;
        if (m < M) g_h2h[(size_t)m * NCLS + col] = __float2half_rn(acc[r]);
    }
}

// ----------------------------------------------------------------
// agg2: one warp per dst node (32 feats), write final fp32 out
// ----------------------------------------------------------------
__global__ __launch_bounds__(256) void k_agg2(const float* __restrict__ b2,
                                              float* __restrict__ out, int n) {
    int gtid = blockIdx.x * blockDim.x + threadIdx.x;
    int d    = gtid >> 5;
    int lane = gtid & 31;
    if (d >= n) return;

    int rs = g_rs[d], re = g_rs[d + 1];
    float acc = 0.f;
    int e = rs;
    for (; e + 1 < re; e += 2) {
        int s0 = g_csrc[e];
        int s1 = g_csrc[e + 1];
        float w0 = g_dinv[s0];
        float w1 = g_dinv[s1];
        float v0 = __half2float(g_h2h[(size_t)s0 * NCLS + lane]);
        float v1 = __half2float(g_h2h[(size_t)s1 * NCLS + lane]);
        acc = fmaf(w0, v0, acc);
        acc = fmaf(w1, v1, acc);
    }
    if (e < re) {
        int s0 = g_csrc[e];
        acc = fmaf(g_dinv[s0], __half2float(g_h2h[(size_t)s0 * NCLS + lane]), acc);
    }

    float di = g_dinv[d];
    float hv = __half2float(g_h2h[(size_t)d * NCLS + lane]);
    out[(size_t)d * NCLS + lane] = fmaf(di, acc, fmaf(di * di, hv, b2[lane]));
}

// ----------------------------------------------------------------
// launch: same DAG as best kernel, but submission order puts k_gemm1
// at global launch index 6 so the harness's ncu (-s 5 -c 1) profiles IT.
// ----------------------------------------------------------------
extern "C" void kernel_launch(void* const* d_in, const int* in_sizes, int n_in,
                              void* d_out, int out_size) {
    const float* x  = (const float*)d_in[0];
    const void*  ei = d_in[1];
    const float* W1 = (const float*)d_in[2];
    const float* b1 = (const float*)d_in[3];
    const float* W2 = (const float*)d_in[4];
    const float* b2 = (const float*)d_in[5];
    float* out = (float*)d_out;

    const int M = in_sizes[0] / INFEAT;     // 100000
    const int E = in_sizes[1] / 2;          // 1600000

    const int T  = 256;
    const int nb = (M + 255) / 256;

    static cudaStream_t s_side = nullptr;
    static cudaEvent_t  ev_fork = nullptr, ev_join = nullptr;
    if (!s_side) {
        cudaStreamCreateWithFlags(&s_side, cudaStreamNonBlocking);
        cudaEventCreateWithFlags(&ev_fork, cudaEventDisableTiming);
        cudaEventCreateWithFlags(&ev_join, cudaEventDisableTiming);
    }

    cudaEventRecord(ev_fork, 0);
    cudaStreamWaitEvent(s_side, ev_fork, 0);

    // launches 1-2 (main): edge parse
    k_setup<<<nb, 256>>>(ei, E, M);
    k_convert<<<(E + T - 1) / T, T>>>(ei, E);

    // launch 3 (side): fp16 conversion
    {
        int nx8 = M * INFEAT / 8;
        int nw8 = INFEAT * HID / 8;
        int gc  = (nx8 + nw8 + T - 1) / T;
        k_cvt<<<gc, T, 0, s_side>>>(x, W1, nx8, nw8);
    }

    // launches 4-5 (main): scan
    k_scan_local<<<nb, 256>>>(M);
    k_scan_bsums<<<1, 512>>>(nb);

    // launch 6 (side): GEMM1  <-- profiled by ncu -s 5 -c 1
    {
        dim3 grid(2, (M + 127) / 128);
        k_gemm1<<<grid, T, 0, s_side>>>(M);
    }
    cudaEventRecord(ev_join, s_side);

    // launches 7-8 (main): finish CSR
    k_scan_add<<<(M + T - 1) / T, T>>>(M, E);
    k_scatter<<<(E + T - 1) / T, T>>>(E);

    // join: aggregation needs both GEMM1 and CSR
    cudaStreamWaitEvent(0, ev_join, 0);

    k_agg1<<<((long long)M * 32 + T - 1) / T, T>>>(b1, M);
    k_gemm2<<<(M + 63) / 64, T>>>(W2, M);
    k_agg2<<<((long long)M * 32 + T - 1) / T, T>>>(b2, out, M);
}